// round 2
// baseline (speedup 1.0000x reference)
#include <cuda_runtime.h>
#include <cstdint>
#include <math.h>

#define BB 16
#define NN 1024
#define DD 256
#define NH 8
#define DKH 32
#define ATTN_SCALE 0.17677669529663687f  // 1/sqrt(32)

// ---------------- scratch (static device globals; no allocation) ----------------
__device__ float g_Qp[BB*NN*DD];       // 16 MB
__device__ float g_Kp[BB*NN*DD];       // 16 MB
__device__ float g_qT[BB*DD*NN];       // 16 MB  (query transposed: [b][c][n])
__device__ float g_kg[BB*DD];
__device__ float g_parth[BB*NH*NN];
__device__ float g_mu1[BB*DD*5];
__device__ float g_mu2[BB*DD*2];
__device__ float g_colpart[2][BB*4*5];
__device__ float g_mupart[2][BB*4*5*DD];
__device__ float g_P1[BB*NN*5];
__device__ float g_P2[BB*NN*2];

// ---------------- f32x2 packed-math helpers (sm_103a) ----------------
__device__ __forceinline__ unsigned long long pack2(float lo, float hi) {
    unsigned long long r;
    asm("mov.b64 %0, {%1, %2};" : "=l"(r) : "f"(lo), "f"(hi));
    return r;
}
__device__ __forceinline__ void unpack2(unsigned long long v, float& lo, float& hi) {
    asm("mov.b64 {%0, %1}, %2;" : "=f"(lo), "=f"(hi) : "l"(v));
}
__device__ __forceinline__ unsigned long long fma2(unsigned long long a, unsigned long long b,
                                                   unsigned long long c) {
    unsigned long long d;
    asm("fma.rn.f32x2 %0, %1, %2, %3;" : "=l"(d) : "l"(a), "l"(b), "l"(c));
    return d;
}
__device__ __forceinline__ unsigned long long add2(unsigned long long a, unsigned long long b) {
    unsigned long long d;
    asm("add.rn.f32x2 %0, %1, %2;" : "=l"(d) : "l"(a), "l"(b));
    return d;
}

// ---------------- helpers ----------------
__device__ __forceinline__ float blockReduceSum256(float v, float* red) {
    #pragma unroll
    for (int off = 16; off; off >>= 1) v += __shfl_down_sync(0xffffffffu, v, off);
    int w = threadIdx.x >> 5;
    if ((threadIdx.x & 31) == 0) red[w] = v;
    __syncthreads();
    if (threadIdx.x < 32) {
        float r = (threadIdx.x < 8) ? red[threadIdx.x] : 0.f;
        #pragma unroll
        for (int off = 4; off; off >>= 1) r += __shfl_down_sync(0xffffffffu, r, off);
        if (threadIdx.x == 0) red[0] = r;
    }
    __syncthreads();
    float out = red[0];
    __syncthreads();
    return out;
}

// ---------------- transpose: qT[b][c][n] = query[b][n][c] ----------------
__global__ __launch_bounds__(256) void transpose_kernel(const float* __restrict__ q,
                                                        float* __restrict__ qT) {
    __shared__ float tile[32][33];
    const int b = blockIdx.z;
    const int n0 = blockIdx.x * 32;
    const int c0 = blockIdx.y * 32;
    const int tx = threadIdx.x, ty = threadIdx.y;
    #pragma unroll
    for (int j = 0; j < 4; j++)
        tile[ty + 8*j][tx] = q[(size_t)(b*NN + n0 + ty + 8*j) * DD + c0 + tx];
    __syncthreads();
    #pragma unroll
    for (int j = 0; j < 4; j++)
        qT[(size_t)(b*DD + c0 + ty + 8*j) * NN + n0 + tx] = tile[tx][ty + 8*j];
}

// ---------------- projection GEMM (f32x2): C[16384,256] = A @ W^T + bias ----------------
__global__ __launch_bounds__(256) void proj_kernel(const float* __restrict__ A,
                                                   const float* __restrict__ W,
                                                   const float* __restrict__ bias,
                                                   float* __restrict__ C) {
    __shared__ float As[8][132];
    __shared__ unsigned long long Bsd[8][128];   // duplicated pairs (w, w)
    const int bm = blockIdx.y * 128;
    const int bn = blockIdx.x * 128;
    const int t  = threadIdx.x;
    const int tx = t & 15, ty = t >> 4;
    const int tn0 = tx * 8, tm0 = ty * 8;
    const int lrow = t >> 1, lk = (t & 1) * 4;

    unsigned long long acc2[4][8];
    #pragma unroll
    for (int ip = 0; ip < 4; ip++)
        #pragma unroll
        for (int j = 0; j < 8; j++) acc2[ip][j] = 0ULL;

    for (int k0 = 0; k0 < 256; k0 += 8) {
        float4 a = *(const float4*)&A[(size_t)(bm + lrow) * 256 + k0 + lk];
        float4 w = *(const float4*)&W[(size_t)(bn + lrow) * 256 + k0 + lk];
        As[lk+0][lrow] = a.x; As[lk+1][lrow] = a.y; As[lk+2][lrow] = a.z; As[lk+3][lrow] = a.w;
        Bsd[lk+0][lrow] = pack2(w.x, w.x);
        Bsd[lk+1][lrow] = pack2(w.y, w.y);
        Bsd[lk+2][lrow] = pack2(w.z, w.z);
        Bsd[lk+3][lrow] = pack2(w.w, w.w);
        __syncthreads();
        #pragma unroll
        for (int k = 0; k < 8; k++) {
            ulonglong2 ra01 = *(const ulonglong2*)&As[k][tm0];
            ulonglong2 ra23 = *(const ulonglong2*)&As[k][tm0 + 4];
            unsigned long long rap[4] = {ra01.x, ra01.y, ra23.x, ra23.y};
            ulonglong2 rb0 = *(const ulonglong2*)&Bsd[k][tn0];
            ulonglong2 rb1 = *(const ulonglong2*)&Bsd[k][tn0 + 2];
            ulonglong2 rb2 = *(const ulonglong2*)&Bsd[k][tn0 + 4];
            ulonglong2 rb3 = *(const ulonglong2*)&Bsd[k][tn0 + 6];
            unsigned long long rbd[8] = {rb0.x, rb0.y, rb1.x, rb1.y, rb2.x, rb2.y, rb3.x, rb3.y};
            #pragma unroll
            for (int ip = 0; ip < 4; ip++)
                #pragma unroll
                for (int j = 0; j < 8; j++)
                    acc2[ip][j] = fma2(rap[ip], rbd[j], acc2[ip][j]);
        }
        __syncthreads();
    }
    #pragma unroll
    for (int ip = 0; ip < 4; ip++) {
        float r0[8], r1[8];
        #pragma unroll
        for (int j = 0; j < 8; j++) {
            float lo, hi;
            unpack2(acc2[ip][j], lo, hi);
            float bj = bias[bn + tn0 + j];
            r0[j] = lo + bj; r1[j] = hi + bj;
        }
        float4* d0 = (float4*)&C[(size_t)(bm + tm0 + 2*ip + 0) * 256 + bn + tn0];
        float4* d1 = (float4*)&C[(size_t)(bm + tm0 + 2*ip + 1) * 256 + bn + tn0];
        d0[0] = make_float4(r0[0], r0[1], r0[2], r0[3]);
        d0[1] = make_float4(r0[4], r0[5], r0[6], r0[7]);
        d1[0] = make_float4(r1[0], r1[1], r1[2], r1[3]);
        d1[1] = make_float4(r1[4], r1[5], r1[6], r1[7]);
    }
}

// ---------------- key_global: kg[b,c] = mean_n Kp[b,n,c] * value[b,n] ----------------
__global__ __launch_bounds__(256) void kg_kernel(const float* __restrict__ Kp,
                                                 const float* __restrict__ value,
                                                 float* __restrict__ kg) {
    int b = blockIdx.x, c = threadIdx.x;
    float a0 = 0.f, a1 = 0.f, a2 = 0.f, a3 = 0.f;
    #pragma unroll 1
    for (int n = 0; n < NN; n += 4) {
        a0 += Kp[(size_t)(b*NN + n + 0) * DD + c] * __ldg(&value[b*NN + n + 0]);
        a1 += Kp[(size_t)(b*NN + n + 1) * DD + c] * __ldg(&value[b*NN + n + 1]);
        a2 += Kp[(size_t)(b*NN + n + 2) * DD + c] * __ldg(&value[b*NN + n + 2]);
        a3 += Kp[(size_t)(b*NN + n + 3) * DD + c] * __ldg(&value[b*NN + n + 3]);
    }
    kg[b*DD + c] = ((a0 + a1) + (a2 + a3)) * (1.0f / NN);
}

// ---------------- flash attention (f32x2 dot), scalar V; 2 queries per thread ----------------
__global__ __launch_bounds__(128) void flash_kernel(const float* __restrict__ Qp,
                                                    const float* __restrict__ Kp,
                                                    const float* __restrict__ value,
                                                    float* __restrict__ parth) {
    const int b = blockIdx.z, h = blockIdx.y;
    const int q0 = blockIdx.x * 256 + threadIdx.x;   // second query = q0 + 128
    __shared__ float Ks[64][32];
    __shared__ float vs[64];

    unsigned long long qa2[16], qb2[16];   // channel pairs
    {
        const ulonglong2* p  = (const ulonglong2*)&Qp[(size_t)(b*NN + q0) * DD + h * DKH];
        const ulonglong2* p2 = (const ulonglong2*)&Qp[(size_t)(b*NN + q0 + 128) * DD + h * DKH];
        #pragma unroll
        for (int i = 0; i < 8; i++) {
            ulonglong2 t = p[i];  qa2[2*i] = t.x; qa2[2*i+1] = t.y;
            ulonglong2 u = p2[i]; qb2[2*i] = u.x; qb2[2*i+1] = u.y;
        }
    }
    float la = 0.f, sa = 0.f, lb = 0.f, sb = 0.f;

    for (int kt = 0; kt < NN; kt += 64) {
        __syncthreads();
        #pragma unroll
        for (int i = 0; i < 16; i++) {
            int idx = i * 128 + threadIdx.x;
            int r = idx >> 5, c2 = idx & 31;
            Ks[r][c2] = Kp[(size_t)(b*NN + kt + r) * DD + h * DKH + c2];
        }
        if (threadIdx.x < 64) vs[threadIdx.x] = value[b*NN + kt + threadIdx.x];
        __syncthreads();
        #pragma unroll 2
        for (int k = 0; k < 64; k++) {
            const ulonglong2* kr = (const ulonglong2*)Ks[k];
            unsigned long long a0 = 0ULL, a1 = 0ULL, b0 = 0ULL, b1 = 0ULL;
            #pragma unroll
            for (int i = 0; i < 8; i++) {
                ulonglong2 kv = kr[i];
                a0 = fma2(qa2[2*i],   kv.x, a0);
                a1 = fma2(qa2[2*i+1], kv.y, a1);
                b0 = fma2(qb2[2*i],   kv.x, b0);
                b1 = fma2(qb2[2*i+1], kv.y, b1);
            }
            float v = vs[k];
            float xlo, xhi, ylo, yhi;
            unpack2(add2(a0, a1), xlo, xhi);
            unpack2(add2(b0, b1), ylo, yhi);
            float xa = (xlo + xhi) * ATTN_SCALE;
            float xb = (ylo + yhi) * ATTN_SCALE;
            float ea = __expf(xa), eb = __expf(xb);
            la += ea; sa += ea * v;
            lb += eb; sb += eb * v;
        }
    }
    parth[(size_t)(b*NH + h) * NN + q0]       = sa / la;
    parth[(size_t)(b*NH + h) * NN + q0 + 128] = sb / lb;
}

// ---------------- combine: f = (1-lam)*part + lam*whole -> out[:, :, 0] ----------------
__global__ __launch_bounds__(256) void combine_kernel(const float* __restrict__ Qp,
                                                      const float* __restrict__ kg,
                                                      const float* __restrict__ parth,
                                                      const float* __restrict__ lamda,
                                                      float* __restrict__ out) {
    int idx = blockIdx.x * 256 + threadIdx.x;   // b*1024+n
    int b = idx >> 10, n = idx & 1023;
    const float4* q   = (const float4*)&Qp[(size_t)idx * DD];
    const float4* kgp = (const float4*)&kg[b * DD];
    float wsum = 0.f;
    #pragma unroll
    for (int h = 0; h < NH; h++) {
        float d = 0.f;
        #pragma unroll
        for (int i = 0; i < 8; i++) {
            float4 qv = q[h*8 + i], kv = kgp[h*8 + i];
            d += qv.x*kv.x + qv.y*kv.y + qv.z*kv.z + qv.w*kv.w;
        }
        wsum += fmaxf(d * ATTN_SCALE, 0.f);
    }
    float whole = wsum * 0.125f;
    float p = 0.f;
    #pragma unroll
    for (int h = 0; h < NH; h++) p += parth[(size_t)(b*NH + h) * NN + n];
    p *= 0.125f;
    float lam = lamda[0];
    out[(size_t)idx * 8] = (1.f - lam) * p + lam * whole;
}

// ---------------- fused PMMS-1 iteration: [finalize mu] -> z-step -> mu-partials ----------------
// grid (4 chunks, 16 b), 256 threads. Ping-pong partial buffers between iterations.
__global__ __launch_bounds__(256) void pmms1_iter_kernel(const float* __restrict__ qT,
                                                         const float* __restrict__ query,
                                                         const float* __restrict__ mu_a,
                                                         const float* __restrict__ mupart_in,
                                                         const float* __restrict__ colpart_in,
                                                         float* __restrict__ mupart_out,
                                                         float* __restrict__ colpart_out,
                                                         int first) {
    __shared__ float mus2[256][8];   // [c][k], padded
    __shared__ float zz2[256][8];    // [n_local][k], padded
    __shared__ float red[8];
    const int chunk = blockIdx.x, b = blockIdx.y;
    const int tid = threadIdx.x;

    // ---- Phase 0: materialize current mu into smem ----
    if (first) {
        for (int i = tid; i < 256 * 5; i += 256) mus2[i / 5][i % 5] = mu_a[i];
        __syncthreads();
    } else {
        const int c = tid;
        float v[5];
        #pragma unroll
        for (int k = 0; k < 5; k++) {
            float cs = 0.f, a = 0.f;
            #pragma unroll
            for (int ch = 0; ch < 4; ch++) {
                cs += colpart_in[(b*4 + ch) * 5 + k];
                a  += mupart_in[(size_t)((b*4 + ch) * 5 + k) * 256 + c];
            }
            v[k] = a / (1e-6f + cs);
        }
        #pragma unroll
        for (int k = 0; k < 5; k++) {
            float s = blockReduceSum256(v[k] * v[k], red);
            mus2[c][k] = v[k] / (1e-6f + sqrtf(s));
        }
        __syncthreads();
    }

    // ---- Phase A: z for this chunk's 256 tokens (thread = token) ----
    {
        const int n = chunk * 256 + tid;
        const float* qp = &qT[(size_t)(b*DD) * NN + n];   // qT[b][c][n], stride NN over c
        float acc[5] = {0.f, 0.f, 0.f, 0.f, 0.f};
        #pragma unroll 4
        for (int c = 0; c < 256; c++) {
            float qv = qp[(size_t)c * NN];
            float4 m4 = *(const float4*)&mus2[c][0];
            float m5 = mus2[c][4];
            acc[0] += qv * m4.x; acc[1] += qv * m4.y; acc[2] += qv * m4.z;
            acc[3] += qv * m4.w; acc[4] += qv * m5;
        }
        float m = acc[0];
        #pragma unroll
        for (int k = 1; k < 5; k++) m = fmaxf(m, acc[k]);
        float sum = 0.f;
        #pragma unroll
        for (int k = 0; k < 5; k++) { acc[k] = __expf(20.f * (acc[k] - m)); sum += acc[k]; }
        float inv = 1.f / sum;
        #pragma unroll
        for (int k = 0; k < 5; k++) {
            acc[k] *= inv;
            zz2[tid][k] = acc[k];
        }
        #pragma unroll
        for (int k = 0; k < 5; k++) {
            float s = blockReduceSum256(acc[k], red);
            if (tid == 0) colpart_out[(b*4 + chunk) * 5 + k] = s;
        }
    }
    __syncthreads();

    // ---- Phase B: mu partials (thread = channel) ----
    {
        const int c = tid;
        const float* qb = &query[(size_t)(b*NN + chunk*256) * DD + c];
        float acc[5] = {0.f, 0.f, 0.f, 0.f, 0.f};
        #pragma unroll 4
        for (int n = 0; n < 256; n++) {
            float qv = qb[(size_t)n * DD];
            float4 z4 = *(const float4*)&zz2[n][0];
            float z5 = zz2[n][4];
            acc[0] += qv * z4.x; acc[1] += qv * z4.y; acc[2] += qv * z4.z;
            acc[3] += qv * z4.w; acc[4] += qv * z5;
        }
        #pragma unroll
        for (int k = 0; k < 5; k++)
            mupart_out[(size_t)((b*4 + chunk) * 5 + k) * 256 + c] = acc[k];
    }
}

// ---------------- PMMS mu finalize: sum chunks, /colsum, l2norm over c ----------------
template<int K>
__global__ __launch_bounds__(256) void mustep_finalize(const float* __restrict__ mupart,
                                                       const float* __restrict__ colpart,
                                                       float* __restrict__ mu) {
    __shared__ float red[8];
    const int b = blockIdx.x, c = threadIdx.x;
    float acc[K];
    #pragma unroll
    for (int k = 0; k < K; k++) {
        float cs = 0.f, a = 0.f;
        #pragma unroll
        for (int ch = 0; ch < 4; ch++) {
            cs += colpart[(b*4 + ch) * K + k];
            a  += mupart[(size_t)((b*4 + ch) * K + k) * 256 + c];
        }
        acc[k] = a / (1e-6f + cs);
    }
    #pragma unroll
    for (int k = 0; k < K; k++) {
        float s = blockReduceSum256(acc[k] * acc[k], red);
        acc[k] = acc[k] / (1e-6f + sqrtf(s));
    }
    #pragma unroll
    for (int k = 0; k < K; k++) mu[(b*256 + c) * K + k] = acc[k];
}

// ---------------- P = softmax(query @ mu), kappa = 1, via qT (coalesced) ----------------
template<int K>
__global__ __launch_bounds__(256) void zstepT_kernel(const float* __restrict__ qT,
                                                     const float* __restrict__ mu,
                                                     float* __restrict__ P) {
    __shared__ float mus2[256][8];
    const int b = blockIdx.y, tid = threadIdx.x;
    for (int i = tid; i < 256 * K; i += 256) mus2[i / K][i % K] = mu[(b*256) * K + i];
    __syncthreads();
    const int n = blockIdx.x * 256 + tid;
    const float* qp = &qT[(size_t)(b*DD) * NN + n];
    float acc[K];
    #pragma unroll
    for (int k = 0; k < K; k++) acc[k] = 0.f;
    #pragma unroll 4
    for (int c = 0; c < 256; c++) {
        float qv = qp[(size_t)c * NN];
        #pragma unroll
        for (int k = 0; k < K; k++) acc[k] += qv * mus2[c][k];
    }
    float m = acc[0];
    #pragma unroll
    for (int k = 1; k < K; k++) m = fmaxf(m, acc[k]);
    float sum = 0.f;
    #pragma unroll
    for (int k = 0; k < K; k++) { acc[k] = __expf(acc[k] - m); sum += acc[k]; }
    float inv = 1.f / sum;
    #pragma unroll
    for (int k = 0; k < K; k++) P[(size_t)(b*NN + n) * K + k] = acc[k] * inv;
}

// ---------------- PMMS-2: node = mu1 (b,256,5), 10 iterations fully in-block ----------------
__global__ __launch_bounds__(256) void pmms2_kernel(const float* __restrict__ mu1,
                                                    const float* __restrict__ mu_b,
                                                    float* __restrict__ mu2) {
    const int b = blockIdx.x, c = threadIdx.x;
    __shared__ float node[256][5];
    __shared__ float zsh[5][2];
    __shared__ float Ssh[10];
    __shared__ float red[8];
    #pragma unroll
    for (int n = 0; n < 5; n++) node[c][n] = mu1[(b*256 + c) * 5 + n];
    float mk0 = mu_b[c*2 + 0], mk1 = mu_b[c*2 + 1];

    for (int it = 0; it < 10; it++) {
        #pragma unroll
        for (int j = 0; j < 10; j++) {
            int n = j >> 1, k = j & 1;
            float v = node[c][n] * (k ? mk1 : mk0);
            float s = blockReduceSum256(v, red);
            if (c == 0) Ssh[j] = s;
        }
        __syncthreads();
        if (c == 0) {
            float csum0 = 0.f, csum1 = 0.f;
            float zt[5][2];
            #pragma unroll
            for (int n = 0; n < 5; n++) {
                float a = 20.f * Ssh[n*2 + 0];
                float q = 20.f * Ssh[n*2 + 1];
                float m = fmaxf(a, q);
                float ea = __expf(a - m), eb = __expf(q - m);
                float inv = 1.f / (ea + eb);
                zt[n][0] = ea * inv; zt[n][1] = eb * inv;
                csum0 += zt[n][0];   csum1 += zt[n][1];
            }
            #pragma unroll
            for (int n = 0; n < 5; n++) {
                zsh[n][0] = zt[n][0] / (1e-6f + csum0);
                zsh[n][1] = zt[n][1] / (1e-6f + csum1);
            }
        }
        __syncthreads();
        float nk0 = 0.f, nk1 = 0.f;
        #pragma unroll
        for (int n = 0; n < 5; n++) {
            nk0 += node[c][n] * zsh[n][0];
            nk1 += node[c][n] * zsh[n][1];
        }
        float s0 = blockReduceSum256(nk0 * nk0, red);
        float s1 = blockReduceSum256(nk1 * nk1, red);
        mk0 = nk0 / (1e-6f + sqrtf(s0));
        mk1 = nk1 / (1e-6f + sqrtf(s1));
        __syncthreads();
    }
    mu2[(b*256 + c) * 2 + 0] = mk0;
    mu2[(b*256 + c) * 2 + 1] = mk1;
}

// ---------------- node_weight: conv(1->16)+BN+ReLU+conv(16->1)+sigmoid gating ----------------
__global__ __launch_bounds__(1024) void nw_kernel(const float* __restrict__ P, int CH,
                                                  const float* __restrict__ w1,
                                                  const float* __restrict__ b1,
                                                  const float* __restrict__ g,
                                                  const float* __restrict__ be,
                                                  const float* __restrict__ w2,
                                                  const float* __restrict__ b2,
                                                  float* __restrict__ out, int outOff) {
    __shared__ float img[34][34];
    __shared__ float t1[8][34][34];
    __shared__ float sw1[144], sw2[144], sb1[16], sg[16], sbe[16];
    const int blk = blockIdx.x;
    const int b = blk / CH, ch = blk % CH;
    const int t = threadIdx.x;
    const int r = t >> 5, c = t & 31;

    for (int i = t; i < 34*34; i += 1024) ((float*)img)[i] = 0.f;
    for (int i = t; i < 8*34*34; i += 1024) ((float*)t1)[i] = 0.f;
    const float bninv = rsqrtf(1.f + 1e-5f);
    if (t < 144) { sw1[t] = w1[t]; sw2[t] = w2[t]; }
    if (t < 16)  { sb1[t] = b1[t]; sg[t] = g[t] * bninv; sbe[t] = be[t]; }
    __syncthreads();

    const int n = r * 32 + c;
    float xv = P[(size_t)((b << 10) + n) * CH + ch];
    img[r + 1][c + 1] = xv;
    float acc = b2[0];

    for (int half = 0; half < 2; half++) {
        __syncthreads();
        #pragma unroll
        for (int oc = 0; oc < 8; oc++) {
            int o = half * 8 + oc;
            float v = sb1[o];
            #pragma unroll
            for (int dy = 0; dy < 3; dy++)
                #pragma unroll
                for (int dx = 0; dx < 3; dx++)
                    v += sw1[o*9 + dy*3 + dx] * img[r + dy][c + dx];
            v = fmaxf(v * sg[o] + sbe[o], 0.f);
            t1[oc][r + 1][c + 1] = v;
        }
        __syncthreads();
        #pragma unroll
        for (int ic = 0; ic < 8; ic++) {
            int i2 = half * 8 + ic;
            #pragma unroll
            for (int dy = 0; dy < 3; dy++)
                #pragma unroll
                for (int dx = 0; dx < 3; dx++)
                    acc += sw2[i2*9 + dy*3 + dx] * t1[ic][r + dy][c + dx];
        }
    }
    float y = 1.f / (1.f + __expf(-acc));
    out[(size_t)((b << 10) + n) * 8 + outOff + ch] = xv * y;
}

// ---------------- launch ----------------
extern "C" void kernel_launch(void* const* d_in, const int* in_sizes, int n_in,
                              void* d_out, int out_size) {
    const float* query = (const float*)d_in[0];
    const float* key   = (const float*)d_in[1];
    const float* value = (const float*)d_in[2];
    const float* lamda = (const float*)d_in[3];
    const float* W0    = (const float*)d_in[4];
    const float* b0    = (const float*)d_in[5];
    const float* W1    = (const float*)d_in[6];
    const float* b1    = (const float*)d_in[7];
    const float* mu_a  = (const float*)d_in[8];
    const float* mu_b  = (const float*)d_in[9];
    const float* nw1_w1 = (const float*)d_in[10];
    const float* nw1_b1 = (const float*)d_in[11];
    const float* nw1_g  = (const float*)d_in[12];
    const float* nw1_be = (const float*)d_in[13];
    const float* nw1_w2 = (const float*)d_in[14];
    const float* nw1_b2 = (const float*)d_in[15];
    const float* nw2_w1 = (const float*)d_in[16];
    const float* nw2_b1 = (const float*)d_in[17];
    const float* nw2_g  = (const float*)d_in[18];
    const float* nw2_be = (const float*)d_in[19];
    const float* nw2_w2 = (const float*)d_in[20];
    const float* nw2_b2 = (const float*)d_in[21];
    float* out = (float*)d_out;

    float *Qp, *Kp, *qT, *kg, *parth, *mu1, *mu2, *P1, *P2;
    float *colpart, *mupart;
    cudaGetSymbolAddress((void**)&Qp, g_Qp);
    cudaGetSymbolAddress((void**)&Kp, g_Kp);
    cudaGetSymbolAddress((void**)&qT, g_qT);
    cudaGetSymbolAddress((void**)&kg, g_kg);
    cudaGetSymbolAddress((void**)&parth, g_parth);
    cudaGetSymbolAddress((void**)&mu1, g_mu1);
    cudaGetSymbolAddress((void**)&mu2, g_mu2);
    cudaGetSymbolAddress((void**)&colpart, g_colpart);
    cudaGetSymbolAddress((void**)&mupart, g_mupart);
    cudaGetSymbolAddress((void**)&P1, g_P1);
    cudaGetSymbolAddress((void**)&P2, g_P2);

    float* mp[2] = {mupart, mupart + BB*4*5*DD};
    float* cp[2] = {colpart, colpart + BB*4*5};

    // Transpose query for coalesced PMMS access
    transpose_kernel<<<dim3(32, 8, 16), dim3(32, 8)>>>(query, qT);

    // Projections
    proj_kernel<<<dim3(2, 128), 256>>>(query, W0, b0, Qp);
    proj_kernel<<<dim3(2, 128), 256>>>(key,   W1, b1, Kp);

    // Attention
    kg_kernel<<<BB, 256>>>(Kp, value, kg);
    flash_kernel<<<dim3(4, NH, BB), 128>>>(Qp, Kp, value, parth);
    combine_kernel<<<64, 256>>>(Qp, kg, parth, lamda, out);

    // PMMS-1 (K=5, 10 fused iterations, ping-pong partials)
    for (int it = 0; it < 10; it++) {
        int ob = it & 1;              // output buffer
        int ib = ob ^ 1;              // input buffer (prev iteration's output)
        pmms1_iter_kernel<<<dim3(4, BB), 256>>>(qT, query, mu_a,
                                                mp[ib], cp[ib], mp[ob], cp[ob],
                                                it == 0 ? 1 : 0);
    }
    mustep_finalize<5><<<BB, 256>>>(mp[1], cp[1], mu1);   // iter 9 wrote buffer 1

    // P1 = softmax(query @ mu1)
    zstepT_kernel<5><<<dim3(4, BB), 256>>>(qT, mu1, P1);

    // PMMS-2 (node = mu1, K=2)
    pmms2_kernel<<<BB, 256>>>(mu1, mu_b, mu2);
    zstepT_kernel<2><<<dim3(4, BB), 256>>>(qT, mu2, P2);

    // node_weight gating
    nw_kernel<<<BB * 5, 1024>>>(P1, 5, nw1_w1, nw1_b1, nw1_g, nw1_be, nw1_w2, nw1_b2, out, 1);
    nw_kernel<<<BB * 2, 1024>>>(P2, 2, nw2_w1, nw2_b1, nw2_g, nw2_be, nw2_w2, nw2_b2, out, 6);
}

// round 3
// speedup vs baseline: 1.3211x; 1.3211x over previous
#include <cuda_runtime.h>
#include <cstdint>
#include <math.h>

#define BB 16
#define NN 1024
#define DD 256
#define NH 8
#define DKH 32
#define ATTN_SCALE 0.17677669529663687f  // 1/sqrt(32)

// ---------------- scratch (static device globals; no allocation) ----------------
__device__ float g_Qp[BB*NN*DD];       // 16 MB
__device__ float g_Kp[BB*NN*DD];       // 16 MB
__device__ float g_qT[BB*DD*NN];       // 16 MB  (query transposed: [b][c][n])
__device__ float g_kg[BB*DD];
__device__ float g_kgpart[BB*8*DD];
__device__ float g_parth[BB*NH*NN];
__device__ float g_mu1[BB*DD*5];
__device__ float g_mu2[BB*DD*2];
__device__ float g_colpart[2][BB*4*5];
__device__ float g_mupart[2][BB*4*5*DD];
__device__ float g_P1[BB*NN*5];
__device__ float g_P2[BB*NN*2];

// ---------------- helpers ----------------
__device__ __forceinline__ float blockReduceSum256(float v, float* red) {
    #pragma unroll
    for (int off = 16; off; off >>= 1) v += __shfl_down_sync(0xffffffffu, v, off);
    int w = threadIdx.x >> 5;
    if ((threadIdx.x & 31) == 0) red[w] = v;
    __syncthreads();
    if (threadIdx.x < 32) {
        float r = (threadIdx.x < 8) ? red[threadIdx.x] : 0.f;
        #pragma unroll
        for (int off = 4; off; off >>= 1) r += __shfl_down_sync(0xffffffffu, r, off);
        if (threadIdx.x == 0) red[0] = r;
    }
    __syncthreads();
    float out = red[0];
    __syncthreads();
    return out;
}

// ---------------- transpose: qT[b][c][n] = query[b][n][c] ----------------
__global__ __launch_bounds__(256) void transpose_kernel(const float* __restrict__ q,
                                                        float* __restrict__ qT) {
    __shared__ float tile[32][33];
    const int b = blockIdx.z;
    const int n0 = blockIdx.x * 32;
    const int c0 = blockIdx.y * 32;
    const int tx = threadIdx.x, ty = threadIdx.y;
    #pragma unroll
    for (int j = 0; j < 4; j++)
        tile[ty + 8*j][tx] = q[(size_t)(b*NN + n0 + ty + 8*j) * DD + c0 + tx];
    __syncthreads();
    #pragma unroll
    for (int j = 0; j < 4; j++)
        qT[(size_t)(b*DD + c0 + ty + 8*j) * NN + n0 + tx] = tile[tx][ty + 8*j];
}

// ---------------- projection GEMM: C[16384,256] = A[16384,256] @ W^T + bias ----------------
__global__ __launch_bounds__(256) void proj_kernel(const float* __restrict__ A,
                                                   const float* __restrict__ W,
                                                   const float* __restrict__ bias,
                                                   float* __restrict__ C) {
    __shared__ float As[8][132];
    __shared__ float Bs[8][132];
    const int bm = blockIdx.y * 128;
    const int bn = blockIdx.x * 128;
    const int t  = threadIdx.x;
    const int tx = t & 15, ty = t >> 4;
    const int tn0 = tx * 8, tm0 = ty * 8;
    const int lrow = t >> 1, lk = (t & 1) * 4;

    float acc[8][8];
    #pragma unroll
    for (int i = 0; i < 8; i++)
        #pragma unroll
        for (int j = 0; j < 8; j++) acc[i][j] = 0.f;

    for (int k0 = 0; k0 < 256; k0 += 8) {
        float4 a = *(const float4*)&A[(size_t)(bm + lrow) * 256 + k0 + lk];
        float4 w = *(const float4*)&W[(size_t)(bn + lrow) * 256 + k0 + lk];
        As[lk+0][lrow] = a.x; As[lk+1][lrow] = a.y; As[lk+2][lrow] = a.z; As[lk+3][lrow] = a.w;
        Bs[lk+0][lrow] = w.x; Bs[lk+1][lrow] = w.y; Bs[lk+2][lrow] = w.z; Bs[lk+3][lrow] = w.w;
        __syncthreads();
        #pragma unroll
        for (int k = 0; k < 8; k++) {
            float4 ra0 = *(const float4*)&As[k][tm0];
            float4 ra1 = *(const float4*)&As[k][tm0 + 4];
            float4 rb0 = *(const float4*)&Bs[k][tn0];
            float4 rb1 = *(const float4*)&Bs[k][tn0 + 4];
            float ra[8] = {ra0.x, ra0.y, ra0.z, ra0.w, ra1.x, ra1.y, ra1.z, ra1.w};
            float rb[8] = {rb0.x, rb0.y, rb0.z, rb0.w, rb1.x, rb1.y, rb1.z, rb1.w};
            #pragma unroll
            for (int i = 0; i < 8; i++)
                #pragma unroll
                for (int j = 0; j < 8; j++) acc[i][j] += ra[i] * rb[j];
        }
        __syncthreads();
    }
    #pragma unroll
    for (int i = 0; i < 8; i++) {
        #pragma unroll
        for (int j = 0; j < 8; j++) acc[i][j] += bias[bn + tn0 + j];
        float4* dst = (float4*)&C[(size_t)(bm + tm0 + i) * 256 + bn + tn0];
        dst[0] = make_float4(acc[i][0], acc[i][1], acc[i][2], acc[i][3]);
        dst[1] = make_float4(acc[i][4], acc[i][5], acc[i][6], acc[i][7]);
    }
}

// ---------------- key_global partials: kgpart[b,chunk,c] = sum_{n in chunk} Kp[b,n,c]*v[b,n] ----------------
__global__ __launch_bounds__(256) void kg_partial_kernel(const float* __restrict__ Kp,
                                                         const float* __restrict__ value,
                                                         float* __restrict__ kgpart) {
    __shared__ float vs[128];
    const int chunk = blockIdx.x, b = blockIdx.y;
    const int c = threadIdx.x;
    const int n0 = chunk * 128;
    if (c < 128) vs[c] = value[b*NN + n0 + c];
    __syncthreads();
    const float* kp = &Kp[(size_t)(b*NN + n0) * DD + c];
    float a0 = 0.f, a1 = 0.f, a2 = 0.f, a3 = 0.f;
    #pragma unroll 4
    for (int n = 0; n < 128; n += 4) {
        a0 += kp[(size_t)(n+0) * DD] * vs[n+0];
        a1 += kp[(size_t)(n+1) * DD] * vs[n+1];
        a2 += kp[(size_t)(n+2) * DD] * vs[n+2];
        a3 += kp[(size_t)(n+3) * DD] * vs[n+3];
    }
    kgpart[(size_t)(b*8 + chunk) * DD + c] = (a0 + a1) + (a2 + a3);
}

__global__ __launch_bounds__(256) void kg_finalize_kernel(const float* __restrict__ kgpart,
                                                          float* __restrict__ kg) {
    const int b = blockIdx.x, c = threadIdx.x;
    float s = 0.f;
    #pragma unroll
    for (int ch = 0; ch < 8; ch++) s += kgpart[(size_t)(b*8 + ch) * DD + c];
    kg[b*DD + c] = s * (1.0f / NN);
}

// ---------------- flash attention with scalar V; 2 queries per thread ----------------
__global__ __launch_bounds__(128) void flash_kernel(const float* __restrict__ Qp,
                                                    const float* __restrict__ Kp,
                                                    const float* __restrict__ value,
                                                    float* __restrict__ parth) {
    const int b = blockIdx.z, h = blockIdx.y;
    const int q0 = blockIdx.x * 256 + threadIdx.x;   // second query = q0 + 128
    __shared__ float Ks[64][32];
    __shared__ float vs[64];

    float qa[32], qb[32];
    {
        const float4* p  = (const float4*)&Qp[(size_t)(b*NN + q0) * DD + h * DKH];
        const float4* p2 = (const float4*)&Qp[(size_t)(b*NN + q0 + 128) * DD + h * DKH];
        #pragma unroll
        for (int i = 0; i < 8; i++) {
            float4 t = p[i];  qa[4*i] = t.x; qa[4*i+1] = t.y; qa[4*i+2] = t.z; qa[4*i+3] = t.w;
            float4 u = p2[i]; qb[4*i] = u.x; qb[4*i+1] = u.y; qb[4*i+2] = u.z; qb[4*i+3] = u.w;
        }
    }
    float la = 0.f, sa = 0.f, lb = 0.f, sb = 0.f;

    for (int kt = 0; kt < NN; kt += 64) {
        __syncthreads();
        #pragma unroll
        for (int i = 0; i < 16; i++) {
            int idx = i * 128 + threadIdx.x;
            int r = idx >> 5, c2 = idx & 31;
            Ks[r][c2] = Kp[(size_t)(b*NN + kt + r) * DD + h * DKH + c2];
        }
        if (threadIdx.x < 64) vs[threadIdx.x] = value[b*NN + kt + threadIdx.x];
        __syncthreads();
        #pragma unroll 2
        for (int k = 0; k < 64; k++) {
            const float4* kr = (const float4*)Ks[k];
            float d0=0.f,d1=0.f,d2=0.f,d3=0.f,e0=0.f,e1=0.f,e2=0.f,e3=0.f;
            #pragma unroll
            for (int i = 0; i < 8; i++) {
                float4 kv = kr[i];
                d0 += qa[4*i]   * kv.x; d1 += qa[4*i+1] * kv.y;
                d2 += qa[4*i+2] * kv.z; d3 += qa[4*i+3] * kv.w;
                e0 += qb[4*i]   * kv.x; e1 += qb[4*i+1] * kv.y;
                e2 += qb[4*i+2] * kv.z; e3 += qb[4*i+3] * kv.w;
            }
            float v  = vs[k];
            float xa = ((d0 + d1) + (d2 + d3)) * ATTN_SCALE;
            float xb = ((e0 + e1) + (e2 + e3)) * ATTN_SCALE;
            float ea = __expf(xa), eb = __expf(xb);
            la += ea; sa += ea * v;
            lb += eb; sb += eb * v;
        }
    }
    parth[(size_t)(b*NH + h) * NN + q0]       = sa / la;
    parth[(size_t)(b*NH + h) * NN + q0 + 128] = sb / lb;
}

// ---------------- combine: f = (1-lam)*part + lam*whole -> out[:, :, 0] ----------------
__global__ __launch_bounds__(256) void combine_kernel(const float* __restrict__ Qp,
                                                      const float* __restrict__ kg,
                                                      const float* __restrict__ parth,
                                                      const float* __restrict__ lamda,
                                                      float* __restrict__ out) {
    int idx = blockIdx.x * 256 + threadIdx.x;   // b*1024+n
    int b = idx >> 10, n = idx & 1023;
    const float4* q   = (const float4*)&Qp[(size_t)idx * DD];
    const float4* kgp = (const float4*)&kg[b * DD];
    float wsum = 0.f;
    #pragma unroll
    for (int h = 0; h < NH; h++) {
        float d = 0.f;
        #pragma unroll
        for (int i = 0; i < 8; i++) {
            float4 qv = q[h*8 + i], kv = kgp[h*8 + i];
            d += qv.x*kv.x + qv.y*kv.y + qv.z*kv.z + qv.w*kv.w;
        }
        wsum += fmaxf(d * ATTN_SCALE, 0.f);
    }
    float whole = wsum * 0.125f;
    float p = 0.f;
    #pragma unroll
    for (int h = 0; h < NH; h++) p += parth[(size_t)(b*NH + h) * NN + n];
    p *= 0.125f;
    float lam = lamda[0];
    out[(size_t)idx * 8] = (1.f - lam) * p + lam * whole;
}

// ---------------- fused PMMS-1 iteration: [finalize mu] -> z-step -> mu-partials ----------------
__global__ __launch_bounds__(256) void pmms1_iter_kernel(const float* __restrict__ qT,
                                                         const float* __restrict__ query,
                                                         const float* __restrict__ mu_a,
                                                         const float* __restrict__ mupart_in,
                                                         const float* __restrict__ colpart_in,
                                                         float* __restrict__ mupart_out,
                                                         float* __restrict__ colpart_out,
                                                         int first) {
    __shared__ float mus2[256][8];   // [c][k], padded
    __shared__ float zz2[256][8];    // [n_local][k], padded
    __shared__ float red[8];
    const int chunk = blockIdx.x, b = blockIdx.y;
    const int tid = threadIdx.x;

    // ---- Phase 0: materialize current mu into smem ----
    if (first) {
        for (int i = tid; i < 256 * 5; i += 256) mus2[i / 5][i % 5] = mu_a[i];
        __syncthreads();
    } else {
        const int c = tid;
        float v[5];
        #pragma unroll
        for (int k = 0; k < 5; k++) {
            float cs = 0.f, a = 0.f;
            #pragma unroll
            for (int ch = 0; ch < 4; ch++) {
                cs += colpart_in[(b*4 + ch) * 5 + k];
                a  += mupart_in[(size_t)((b*4 + ch) * 5 + k) * 256 + c];
            }
            v[k] = a / (1e-6f + cs);
        }
        #pragma unroll
        for (int k = 0; k < 5; k++) {
            float s = blockReduceSum256(v[k] * v[k], red);
            mus2[c][k] = v[k] / (1e-6f + sqrtf(s));
        }
        __syncthreads();
    }

    // ---- Phase A: z for this chunk's 256 tokens (thread = token) ----
    {
        const int n = chunk * 256 + tid;
        const float* qp = &qT[(size_t)(b*DD) * NN + n];   // qT[b][c][n], stride NN over c
        float acc[5] = {0.f, 0.f, 0.f, 0.f, 0.f};
        #pragma unroll 4
        for (int c = 0; c < 256; c++) {
            float qv = qp[(size_t)c * NN];
            float4 m4 = *(const float4*)&mus2[c][0];
            float m5 = mus2[c][4];
            acc[0] += qv * m4.x; acc[1] += qv * m4.y; acc[2] += qv * m4.z;
            acc[3] += qv * m4.w; acc[4] += qv * m5;
        }
        float m = acc[0];
        #pragma unroll
        for (int k = 1; k < 5; k++) m = fmaxf(m, acc[k]);
        float sum = 0.f;
        #pragma unroll
        for (int k = 0; k < 5; k++) { acc[k] = __expf(20.f * (acc[k] - m)); sum += acc[k]; }
        float inv = 1.f / sum;
        #pragma unroll
        for (int k = 0; k < 5; k++) {
            acc[k] *= inv;
            zz2[tid][k] = acc[k];
        }
        #pragma unroll
        for (int k = 0; k < 5; k++) {
            float s = blockReduceSum256(acc[k], red);
            if (tid == 0) colpart_out[(b*4 + chunk) * 5 + k] = s;
        }
    }
    __syncthreads();

    // ---- Phase B: mu partials (thread = channel) ----
    {
        const int c = tid;
        const float* qb = &query[(size_t)(b*NN + chunk*256) * DD + c];
        float acc[5] = {0.f, 0.f, 0.f, 0.f, 0.f};
        #pragma unroll 4
        for (int n = 0; n < 256; n++) {
            float qv = qb[(size_t)n * DD];
            float4 z4 = *(const float4*)&zz2[n][0];
            float z5 = zz2[n][4];
            acc[0] += qv * z4.x; acc[1] += qv * z4.y; acc[2] += qv * z4.z;
            acc[3] += qv * z4.w; acc[4] += qv * z5;
        }
        #pragma unroll
        for (int k = 0; k < 5; k++)
            mupart_out[(size_t)((b*4 + chunk) * 5 + k) * 256 + c] = acc[k];
    }
}

// ---------------- PMMS mu finalize: sum chunks, /colsum, l2norm over c ----------------
template<int K>
__global__ __launch_bounds__(256) void mustep_finalize(const float* __restrict__ mupart,
                                                       const float* __restrict__ colpart,
                                                       float* __restrict__ mu) {
    __shared__ float red[8];
    const int b = blockIdx.x, c = threadIdx.x;
    float acc[K];
    #pragma unroll
    for (int k = 0; k < K; k++) {
        float cs = 0.f, a = 0.f;
        #pragma unroll
        for (int ch = 0; ch < 4; ch++) {
            cs += colpart[(b*4 + ch) * K + k];
            a  += mupart[(size_t)((b*4 + ch) * K + k) * 256 + c];
        }
        acc[k] = a / (1e-6f + cs);
    }
    #pragma unroll
    for (int k = 0; k < K; k++) {
        float s = blockReduceSum256(acc[k] * acc[k], red);
        acc[k] = acc[k] / (1e-6f + sqrtf(s));
    }
    #pragma unroll
    for (int k = 0; k < K; k++) mu[(b*256 + c) * K + k] = acc[k];
}

// ---------------- P = softmax(query @ mu), kappa = 1, via qT (coalesced) ----------------
template<int K>
__global__ __launch_bounds__(256) void zstepT_kernel(const float* __restrict__ qT,
                                                     const float* __restrict__ mu,
                                                     float* __restrict__ P) {
    __shared__ float mus2[256][8];
    const int b = blockIdx.y, tid = threadIdx.x;
    for (int i = tid; i < 256 * K; i += 256) mus2[i / K][i % K] = mu[(b*256) * K + i];
    __syncthreads();
    const int n = blockIdx.x * 256 + tid;
    const float* qp = &qT[(size_t)(b*DD) * NN + n];
    float acc[K];
    #pragma unroll
    for (int k = 0; k < K; k++) acc[k] = 0.f;
    #pragma unroll 4
    for (int c = 0; c < 256; c++) {
        float qv = qp[(size_t)c * NN];
        #pragma unroll
        for (int k = 0; k < K; k++) acc[k] += qv * mus2[c][k];
    }
    float m = acc[0];
    #pragma unroll
    for (int k = 1; k < K; k++) m = fmaxf(m, acc[k]);
    float sum = 0.f;
    #pragma unroll
    for (int k = 0; k < K; k++) { acc[k] = __expf(acc[k] - m); sum += acc[k]; }
    float inv = 1.f / sum;
    #pragma unroll
    for (int k = 0; k < K; k++) P[(size_t)(b*NN + n) * K + k] = acc[k] * inv;
}

// ---------------- PMMS-2: node = mu1 (b,256,5), 10 iterations fully in-block ----------------
__global__ __launch_bounds__(256) void pmms2_kernel(const float* __restrict__ mu1,
                                                    const float* __restrict__ mu_b,
                                                    float* __restrict__ mu2) {
    const int b = blockIdx.x, c = threadIdx.x;
    __shared__ float node[256][5];
    __shared__ float zsh[5][2];
    __shared__ float Ssh[10];
    __shared__ float red[8];
    #pragma unroll
    for (int n = 0; n < 5; n++) node[c][n] = mu1[(b*256 + c) * 5 + n];
    float mk0 = mu_b[c*2 + 0], mk1 = mu_b[c*2 + 1];

    for (int it = 0; it < 10; it++) {
        #pragma unroll
        for (int j = 0; j < 10; j++) {
            int n = j >> 1, k = j & 1;
            float v = node[c][n] * (k ? mk1 : mk0);
            float s = blockReduceSum256(v, red);
            if (c == 0) Ssh[j] = s;
        }
        __syncthreads();
        if (c == 0) {
            float csum0 = 0.f, csum1 = 0.f;
            float zt[5][2];
            #pragma unroll
            for (int n = 0; n < 5; n++) {
                float a = 20.f * Ssh[n*2 + 0];
                float q = 20.f * Ssh[n*2 + 1];
                float m = fmaxf(a, q);
                float ea = __expf(a - m), eb = __expf(q - m);
                float inv = 1.f / (ea + eb);
                zt[n][0] = ea * inv; zt[n][1] = eb * inv;
                csum0 += zt[n][0];   csum1 += zt[n][1];
            }
            #pragma unroll
            for (int n = 0; n < 5; n++) {
                zsh[n][0] = zt[n][0] / (1e-6f + csum0);
                zsh[n][1] = zt[n][1] / (1e-6f + csum1);
            }
        }
        __syncthreads();
        float nk0 = 0.f, nk1 = 0.f;
        #pragma unroll
        for (int n = 0; n < 5; n++) {
            nk0 += node[c][n] * zsh[n][0];
            nk1 += node[c][n] * zsh[n][1];
        }
        float s0 = blockReduceSum256(nk0 * nk0, red);
        float s1 = blockReduceSum256(nk1 * nk1, red);
        mk0 = nk0 / (1e-6f + sqrtf(s0));
        mk1 = nk1 / (1e-6f + sqrtf(s1));
        __syncthreads();
    }
    mu2[(b*256 + c) * 2 + 0] = mk0;
    mu2[(b*256 + c) * 2 + 1] = mk1;
}

// ---------------- node_weight: conv(1->16)+BN+ReLU+conv(16->1)+sigmoid gating ----------------
__global__ __launch_bounds__(1024) void nw_kernel(const float* __restrict__ P, int CH,
                                                  const float* __restrict__ w1,
                                                  const float* __restrict__ b1,
                                                  const float* __restrict__ g,
                                                  const float* __restrict__ be,
                                                  const float* __restrict__ w2,
                                                  const float* __restrict__ b2,
                                                  float* __restrict__ out, int outOff) {
    __shared__ float img[34][34];
    __shared__ float t1[8][34][34];
    __shared__ float sw1[144], sw2[144], sb1[16], sg[16], sbe[16];
    const int blk = blockIdx.x;
    const int b = blk / CH, ch = blk % CH;
    const int t = threadIdx.x;
    const int r = t >> 5, c = t & 31;

    for (int i = t; i < 34*34; i += 1024) ((float*)img)[i] = 0.f;
    for (int i = t; i < 8*34*34; i += 1024) ((float*)t1)[i] = 0.f;
    const float bninv = rsqrtf(1.f + 1e-5f);
    if (t < 144) { sw1[t] = w1[t]; sw2[t] = w2[t]; }
    if (t < 16)  { sb1[t] = b1[t]; sg[t] = g[t] * bninv; sbe[t] = be[t]; }
    __syncthreads();

    const int n = r * 32 + c;
    float xv = P[(size_t)((b << 10) + n) * CH + ch];
    img[r + 1][c + 1] = xv;
    float acc = b2[0];

    for (int half = 0; half < 2; half++) {
        __syncthreads();
        #pragma unroll
        for (int oc = 0; oc < 8; oc++) {
            int o = half * 8 + oc;
            float v = sb1[o];
            #pragma unroll
            for (int dy = 0; dy < 3; dy++)
                #pragma unroll
                for (int dx = 0; dx < 3; dx++)
                    v += sw1[o*9 + dy*3 + dx] * img[r + dy][c + dx];
            v = fmaxf(v * sg[o] + sbe[o], 0.f);
            t1[oc][r + 1][c + 1] = v;
        }
        __syncthreads();
        #pragma unroll
        for (int ic = 0; ic < 8; ic++) {
            int i2 = half * 8 + ic;
            #pragma unroll
            for (int dy = 0; dy < 3; dy++)
                #pragma unroll
                for (int dx = 0; dx < 3; dx++)
                    acc += sw2[i2*9 + dy*3 + dx] * t1[ic][r + dy][c + dx];
        }
    }
    float y = 1.f / (1.f + __expf(-acc));
    out[(size_t)((b << 10) + n) * 8 + outOff + ch] = xv * y;
}

// ---------------- launch ----------------
extern "C" void kernel_launch(void* const* d_in, const int* in_sizes, int n_in,
                              void* d_out, int out_size) {
    const float* query = (const float*)d_in[0];
    const float* key   = (const float*)d_in[1];
    const float* value = (const float*)d_in[2];
    const float* lamda = (const float*)d_in[3];
    const float* W0    = (const float*)d_in[4];
    const float* b0    = (const float*)d_in[5];
    const float* W1    = (const float*)d_in[6];
    const float* b1    = (const float*)d_in[7];
    const float* mu_a  = (const float*)d_in[8];
    const float* mu_b  = (const float*)d_in[9];
    const float* nw1_w1 = (const float*)d_in[10];
    const float* nw1_b1 = (const float*)d_in[11];
    const float* nw1_g  = (const float*)d_in[12];
    const float* nw1_be = (const float*)d_in[13];
    const float* nw1_w2 = (const float*)d_in[14];
    const float* nw1_b2 = (const float*)d_in[15];
    const float* nw2_w1 = (const float*)d_in[16];
    const float* nw2_b1 = (const float*)d_in[17];
    const float* nw2_g  = (const float*)d_in[18];
    const float* nw2_be = (const float*)d_in[19];
    const float* nw2_w2 = (const float*)d_in[20];
    const float* nw2_b2 = (const float*)d_in[21];
    float* out = (float*)d_out;

    float *Qp, *Kp, *qT, *kg, *kgpart, *parth, *mu1, *mu2, *P1, *P2;
    float *colpart, *mupart;
    cudaGetSymbolAddress((void**)&Qp, g_Qp);
    cudaGetSymbolAddress((void**)&Kp, g_Kp);
    cudaGetSymbolAddress((void**)&qT, g_qT);
    cudaGetSymbolAddress((void**)&kg, g_kg);
    cudaGetSymbolAddress((void**)&kgpart, g_kgpart);
    cudaGetSymbolAddress((void**)&parth, g_parth);
    cudaGetSymbolAddress((void**)&mu1, g_mu1);
    cudaGetSymbolAddress((void**)&mu2, g_mu2);
    cudaGetSymbolAddress((void**)&colpart, g_colpart);
    cudaGetSymbolAddress((void**)&mupart, g_mupart);
    cudaGetSymbolAddress((void**)&P1, g_P1);
    cudaGetSymbolAddress((void**)&P2, g_P2);

    float* mp[2] = {mupart, mupart + BB*4*5*DD};
    float* cp[2] = {colpart, colpart + BB*4*5};

    // Transpose query for coalesced PMMS access
    transpose_kernel<<<dim3(32, 8, 16), dim3(32, 8)>>>(query, qT);

    // Projections
    proj_kernel<<<dim3(2, 128), 256>>>(query, W0, b0, Qp);
    proj_kernel<<<dim3(2, 128), 256>>>(key,   W1, b1, Kp);

    // Attention
    kg_partial_kernel<<<dim3(8, BB), 256>>>(Kp, value, kgpart);
    kg_finalize_kernel<<<BB, 256>>>(kgpart, kg);
    flash_kernel<<<dim3(4, NH, BB), 128>>>(Qp, Kp, value, parth);
    combine_kernel<<<64, 256>>>(Qp, kg, parth, lamda, out);

    // PMMS-1 (K=5, 10 fused iterations, ping-pong partials)
    for (int it = 0; it < 10; it++) {
        int ob = it & 1;              // output buffer
        int ib = ob ^ 1;              // input buffer (prev iteration's output)
        pmms1_iter_kernel<<<dim3(4, BB), 256>>>(qT, query, mu_a,
                                                mp[ib], cp[ib], mp[ob], cp[ob],
                                                it == 0 ? 1 : 0);
    }
    mustep_finalize<5><<<BB, 256>>>(mp[1], cp[1], mu1);   // iter 9 wrote buffer 1

    // P1 = softmax(query @ mu1)
    zstepT_kernel<5><<<dim3(4, BB), 256>>>(qT, mu1, P1);

    // PMMS-2 (node = mu1, K=2)
    pmms2_kernel<<<BB, 256>>>(mu1, mu_b, mu2);
    zstepT_kernel<2><<<dim3(4, BB), 256>>>(qT, mu2, P2);

    // node_weight gating
    nw_kernel<<<BB * 5, 1024>>>(P1, 5, nw1_w1, nw1_b1, nw1_g, nw1_be, nw1_w2, nw1_b2, out, 1);
    nw_kernel<<<BB * 2, 1024>>>(P2, 2, nw2_w1, nw2_b1, nw2_g, nw2_be, nw2_w2, nw2_b2, out, 6);
}